// round 7
// baseline (speedup 1.0000x reference)
#include <cuda_runtime.h>

#define DD 160
#define HH 192
#define WW 160
#define DHW (DD*HH*WW)

// output tile per block
#define TX 32
#define TY 8
#define TZ 4
// staged window: [base-5, base+tile+5] (+1 for the far corner)
#define PLO 5
#define WX (TX + 11)   // 43
#define WY (TY + 11)   // 19
#define WZ (TZ + 11)   // 15
#define SN (WZ * WY * WX)  // 12255 floats = 49020 B (< 48KB static limit)

__device__ __forceinline__ float sample1_global(const float* __restrict__ v,
                                                float ix, float iy, float iz) {
    if (ix <= -1.0f || ix >= (float)WW ||
        iy <= -1.0f || iy >= (float)HH ||
        iz <= -1.0f || iz >= (float)DD) return 0.0f;
    float x0f = floorf(ix), y0f = floorf(iy), z0f = floorf(iz);
    int x0 = (int)x0f, y0 = (int)y0f, z0 = (int)z0f;
    float tx = ix - x0f, ty = iy - y0f, tz = iz - z0f;
    float acc = 0.0f;
    #pragma unroll
    for (int dz = 0; dz < 2; dz++) {
        int zc = z0 + dz;
        if ((unsigned)zc >= (unsigned)DD) continue;
        float wz = dz ? tz : 1.0f - tz;
        #pragma unroll
        for (int dy = 0; dy < 2; dy++) {
            int yc = y0 + dy;
            if ((unsigned)yc >= (unsigned)HH) continue;
            float wy = dy ? ty : 1.0f - ty;
            float wzy = wz * wy;
            unsigned base = ((unsigned)zc * HH + (unsigned)yc) * WW;
            #pragma unroll
            for (int dx = 0; dx < 2; dx++) {
                int xc = x0 + dx;
                if ((unsigned)xc >= (unsigned)WW) continue;
                float w = wzy * (dx ? tx : 1.0f - tx);
                acc = fmaf(w, __ldg(v + base + (unsigned)xc), acc);
            }
        }
    }
    return acc;
}

__device__ __forceinline__ void sample3(const float* __restrict__ v,
                                        float ix, float iy, float iz,
                                        float& o0, float& o1, float& o2) {
    o0 = 0.0f; o1 = 0.0f; o2 = 0.0f;
    // practically always fully out of bounds -> warp-uniform early-out
    if (ix <= -1.0f || ix >= (float)WW ||
        iy <= -1.0f || iy >= (float)HH ||
        iz <= -1.0f || iz >= (float)DD) return;
    float x0f = floorf(ix), y0f = floorf(iy), z0f = floorf(iz);
    int x0 = (int)x0f, y0 = (int)y0f, z0 = (int)z0f;
    float tx = ix - x0f, ty = iy - y0f, tz = iz - z0f;
    #pragma unroll
    for (int dz = 0; dz < 2; dz++) {
        int zc = z0 + dz;
        if ((unsigned)zc >= (unsigned)DD) continue;
        float wz = dz ? tz : 1.0f - tz;
        #pragma unroll
        for (int dy = 0; dy < 2; dy++) {
            int yc = y0 + dy;
            if ((unsigned)yc >= (unsigned)HH) continue;
            float wy = dy ? ty : 1.0f - ty;
            float wzy = wz * wy;
            unsigned base = ((unsigned)zc * HH + (unsigned)yc) * WW;
            #pragma unroll
            for (int dx = 0; dx < 2; dx++) {
                int xc = x0 + dx;
                if ((unsigned)xc >= (unsigned)WW) continue;
                float w = wzy * (dx ? tx : 1.0f - tx);
                unsigned off = base + (unsigned)xc;
                o0 = fmaf(w, __ldg(v + off), o0);
                o1 = fmaf(w, __ldg(v + DHW + off), o1);
                o2 = fmaf(w, __ldg(v + 2u*DHW + off), o2);
            }
        }
    }
}

__global__ void __launch_bounds__(256) st_kernel(
                          const float* __restrict__ src,
                          const float* __restrict__ flow1,
                          const float* __restrict__ flow2,
                          const float* __restrict__ rf_p,
                          float* __restrict__ out) {
    __shared__ float tile[SN];

    const int xb = blockIdx.x * TX;
    const int yb = blockIdx.y * TY;
    const int zb = blockIdx.z * TZ;
    const int wxb = xb - PLO, wyb = yb - PLO, wzb = zb - PLO;

    const int tid = threadIdx.y * 32 + threadIdx.x;

    // ---- cooperative fill of src window (zero-fill out-of-volume) ----
    for (int i = tid; i < SN; i += 256) {
        int xi = i % WX;
        int t  = i / WX;
        int yi = t % WY;
        int zi = t / WY;
        int gx = wxb + xi, gy = wyb + yi, gz = wzb + zi;
        float val = 0.0f;
        if ((unsigned)gx < (unsigned)WW && (unsigned)gy < (unsigned)HH &&
            (unsigned)gz < (unsigned)DD)
            val = __ldg(src + ((unsigned)gz * HH + (unsigned)gy) * WW + (unsigned)gx);
        tile[i] = val;
    }
    __syncthreads();

    const int x = xb + threadIdx.x;
    const int y = yb + threadIdx.y;
    const float xf = (float)x, yf = (float)y;
    const float rf = __ldg(rf_p);

    unsigned idx0 = ((unsigned)zb * HH + (unsigned)y) * WW + (unsigned)x;

    // front-batched flow2 loads across the 4 z (MLP = 12)
    float f2z[TZ], f2y[TZ], f2x[TZ];
    #pragma unroll
    for (int j = 0; j < TZ; j++) {
        unsigned idx = idx0 + j * (unsigned)(HH * WW);
        f2z[j] = __ldg(flow2 + idx);
        f2y[j] = __ldg(flow2 + DHW + idx);
        f2x[j] = __ldg(flow2 + 2u*DHW + idx);
    }

    #pragma unroll
    for (int j = 0; j < TZ; j++) {
        unsigned idx = idx0 + j * (unsigned)(HH * WW);
        float zf = (float)(zb + j);

        // grid2 = grid + flow2 * rf  (grid analytic)
        float g2z = zf + f2z[j] * rf;
        float g2y = yf + f2y[j] * rf;
        float g2x = xf + f2x[j] * rf;

        // grid_sample(flow1, grid2) unnorm (align_corners=False)
        float ix1 = ((g2x + 1.0f) * (float)WW - 1.0f) * 0.5f;
        float iy1 = ((g2y + 1.0f) * (float)HH - 1.0f) * 0.5f;
        float iz1 = ((g2z + 1.0f) * (float)DD - 1.0f) * 0.5f;

        float w0, w1, w2;
        sample3(flow1, ix1, iy1, iz1, w0, w1, w2);

        // out_flow = flow1_warped + flow2
        float oz = w0 + f2z[j];
        float oy = w1 + f2y[j];
        float ox = w2 + f2x[j];

        // new_locs_total -> normalize -> unnorm (same fp order as reference)
        float vz = zf + oz * rf;
        float vy = yf + oy * rf;
        float vx = xf + ox * rf;

        float nz = 2.0f * (vz / (float)(DD - 1) - 0.5f);
        float ny = 2.0f * (vy / (float)(HH - 1) - 0.5f);
        float nx = 2.0f * (vx / (float)(WW - 1) - 0.5f);

        float sx = ((nx + 1.0f) * (float)WW - 1.0f) * 0.5f;
        float sy = ((ny + 1.0f) * (float)HH - 1.0f) * 0.5f;
        float sz = ((nz + 1.0f) * (float)DD - 1.0f) * 0.5f;

        // ---- trilinear sample of src: smem fast path ----
        float x0f = floorf(sx), y0f = floorf(sy), z0f = floorf(sz);
        int x0 = (int)x0f, y0 = (int)y0f, z0 = (int)z0f;
        float txf = sx - x0f, tyf = sy - y0f, tzf = sz - z0f;

        int xi = x0 - wxb, yi = y0 - wyb, zi = z0 - wzb;
        bool inwin = ((unsigned)xi < (unsigned)(WX - 1)) &
                     ((unsigned)yi < (unsigned)(WY - 1)) &
                     ((unsigned)zi < (unsigned)(WZ - 1));

        float img;
        if (inwin) {
            // volume-bounds masks (window cells outside volume are zero-filled,
            // and their weights are zeroed here -> exact zeros padding)
            float wx0 = ((unsigned)x0       < (unsigned)WW) ? (1.0f - txf) : 0.0f;
            float wx1 = ((unsigned)(x0 + 1) < (unsigned)WW) ? txf : 0.0f;
            float wy0 = ((unsigned)y0       < (unsigned)HH) ? (1.0f - tyf) : 0.0f;
            float wy1 = ((unsigned)(y0 + 1) < (unsigned)HH) ? tyf : 0.0f;
            float wz0 = ((unsigned)z0       < (unsigned)DD) ? (1.0f - tzf) : 0.0f;
            float wz1 = ((unsigned)(z0 + 1) < (unsigned)DD) ? tzf : 0.0f;

            int b00 = (zi * WY + yi) * WX + xi;
            int b01 = b00 + WX;
            int b10 = b00 + WY * WX;
            int b11 = b10 + WX;

            float r00 = fmaf(tile[b00], wx0, tile[b00 + 1] * wx1);
            float r01 = fmaf(tile[b01], wx0, tile[b01 + 1] * wx1);
            float r10 = fmaf(tile[b10], wx0, tile[b10 + 1] * wx1);
            float r11 = fmaf(tile[b11], wx0, tile[b11 + 1] * wx1);

            img = wz0 * fmaf(wy0, r00, wy1 * r01)
                + wz1 * fmaf(wy0, r10, wy1 * r11);
        } else {
            img = sample1_global(src, sx, sy, sz);
        }

        out[idx]          = img;
        out[DHW + idx]    = oz;
        out[2u*DHW + idx] = oy;
        out[3u*DHW + idx] = ox;
    }
}

extern "C" void kernel_launch(void* const* d_in, const int* in_sizes, int n_in,
                              void* d_out, int out_size) {
    const float* src   = (const float*)d_in[0];
    const float* flow1 = (const float*)d_in[1];
    const float* flow2 = (const float*)d_in[2];
    // d_in[3] meshgrid — analytic, not loaded
    const float* rf    = (const float*)d_in[4];
    float* out = (float*)d_out;

    dim3 block(32, 8);
    dim3 grid(WW / TX, HH / TY, DD / TZ);
    st_kernel<<<grid, block>>>(src, flow1, flow2, rf, out);
}